// round 4
// baseline (speedup 1.0000x reference)
#include <cuda_runtime.h>
#include <cuda_fp16.h>
#include <stdint.h>

#define B_SZ     4096
#define D0       1024
#define D1       8192
#define D2       8192
#define D3       10240
#define NNEUR    (D1 + D2 + D3)     // 26624
#define KCLS     10
#define GRP      (D3 / KCLS)        // 1024
#define TAU      30.0f
#define ROWS     4                  // batch rows per CTA (4096/4 = 1024 CTAs, exact)
#define R2       (ROWS / 2)
#define NTHREADS 1024
#define NWARP    (NTHREADS / 32)    // 32
#define CELLS    256                // 16 a-bank-pairs x 16 b-bank-pairs

// -------- final (permuted) per-neuron metadata --------
__device__ uint32_t g_idx[NNEUR];   // ia | (ib<<16)   (position-space indices)
__device__ uint32_t g_c01[NNEUR];   // half2(c0,c1)
__device__ uint32_t g_c23[NNEUR];   // half2(c2,c3)

// -------- staging (unpermuted) + permutations --------
__device__ uint32_t s_idx[NNEUR];
__device__ uint32_t s_c01[NNEUR];
__device__ uint32_t s_c23[NNEUR];
__device__ uint16_t d_perm1[D1], d_inv1[D1];
__device__ uint16_t d_perm2[D2], d_inv2[D2];
__device__ uint16_t d_perm3[D3];    // per-group (local) permutation

__constant__ float OPC[16][4] = {
    {0.f, 0.f, 0.f, 0.f}, {0.f, 0.f, 0.f, 1.f}, {0.f, 1.f, 0.f, -1.f}, {0.f, 1.f, 0.f, 0.f},
    {0.f, 0.f, 1.f, -1.f}, {0.f, 0.f, 1.f, 0.f}, {0.f, 1.f, 1.f, -2.f}, {0.f, 1.f, 1.f, -1.f},
    {1.f, -1.f, -1.f, 1.f}, {1.f, -1.f, -1.f, 2.f}, {1.f, 0.f, -1.f, 0.f}, {1.f, 0.f, -1.f, 1.f},
    {1.f, -1.f, 0.f, 0.f}, {1.f, -1.f, 0.f, 1.f}, {1.f, 0.f, 0.f, -1.f}, {1.f, 0.f, 0.f, 0.f}};

__global__ void precompute_kernel(
    const float* __restrict__ w1, const float* __restrict__ w2, const float* __restrict__ w3,
    const int* __restrict__ ia1, const int* __restrict__ ib1,
    const int* __restrict__ ia2, const int* __restrict__ ib2,
    const int* __restrict__ ia3, const int* __restrict__ ib3)
{
    int j = blockIdx.x * blockDim.x + threadIdx.x;
    if (j >= NNEUR) return;
    const float* w; int ia, ib;
    if (j < D1)            { w = w1 + (size_t)j * 16;               ia = ia1[j];            ib = ib1[j]; }
    else if (j < D1 + D2)  { int k = j - D1;      w = w2 + (size_t)k * 16; ia = ia2[k]; ib = ib2[k]; }
    else                   { int k = j - D1 - D2; w = w3 + (size_t)k * 16; ia = ia3[k]; ib = ib3[k]; }

    float v[16]; float m = -3.4e38f;
#pragma unroll
    for (int i = 0; i < 16; i++) { v[i] = w[i]; m = fmaxf(m, v[i]); }
    float s = 0.f;
#pragma unroll
    for (int i = 0; i < 16; i++) { v[i] = expf(v[i] - m); s += v[i]; }
    float inv = 1.f / s;
    float c0 = 0.f, c1 = 0.f, c2 = 0.f, c3 = 0.f;
#pragma unroll
    for (int i = 0; i < 16; i++) {
        float p = v[i] * inv;
        c0 = fmaf(p, OPC[i][0], c0);
        c1 = fmaf(p, OPC[i][1], c1);
        c2 = fmaf(p, OPC[i][2], c2);
        c3 = fmaf(p, OPC[i][3], c3);
    }
    s_idx[j] = (uint32_t)ia | ((uint32_t)ib << 16);
    __half2 h01 = __floats2half2_rn(c0, c1);
    __half2 h23 = __floats2half2_rn(c2, c3);
    s_c01[j] = *reinterpret_cast<uint32_t*>(&h01);
    s_c23[j] = *reinterpret_cast<uint32_t*>(&h23);
}

// ---- bank-dealing permutation builder -----------------------------------
// One CTA builds the permutation for D items (blockIdx.x selects the group).
// Deterministic: counts via __match_any, offsets via in-smem scans. No atomics.
template<int D>
__global__ void __launch_bounds__(1024, 1)
build_perm_kernel(int metaBase, const uint16_t* __restrict__ remap,
                  uint16_t* __restrict__ perm, uint16_t* __restrict__ inv)
{
    constexpr int ITEMS = D / 1024;
    constexpr int VW    = D / 32;      // virtual warps
    constexpr int CAP   = D / CELLS;   // slots per cell

    extern __shared__ uint16_t sm[];
    uint16_t (*off)[CELLS] = reinterpret_cast<uint16_t(*)[CELLS]>(sm); // VW x CELLS
    uint16_t* csize = sm + VW * CELLS;          // CELLS
    uint16_t* exoff = csize + CELLS;            // CELLS (inclusive scan of excess)
    uint16_t* ufoff = exoff + CELLS;            // CELLS (inclusive scan of unfilled)
    uint16_t* ufp   = ufoff + CELLS;            // up to D unfilled positions

    const int tid  = threadIdx.x;
    const int lane = tid & 31;
    const int w    = tid >> 5;
    const uint32_t ltm = (1u << lane) - 1u;
    const int grpMeta = metaBase + blockIdx.x * D;

    for (int i = tid; i < VW * CELLS; i += 1024) sm[i] = 0;
    __syncthreads();

    int mycell[ITEMS], mylr[ITEMS];
#pragma unroll
    for (int k = 0; k < ITEMS; k++) {
        int j = k * 1024 + tid;
        uint32_t pk = s_idx[grpMeta + j];
        uint32_t a = pk & 0xffffu, b = pk >> 16;
        if (remap) { a = remap[a]; b = remap[b]; }
        int cell = (int)((a & 15u) * 16u + (b & 15u));
        uint32_t mask = __match_any_sync(0xffffffffu, cell);
        mycell[k] = cell;
        mylr[k]   = __popc(mask & ltm);
        if ((mask & ltm) == 0)                         // leader for this cell
            off[k * 32 + w][cell] = (uint16_t)__popc(mask);
    }
    __syncthreads();

    // per-cell exclusive scan over virtual warps, + cell sizes + excess/unfilled counts
    if (tid < CELLS) {
        int c = tid; uint16_t base = 0;
        for (int v = 0; v < VW; v++) { uint16_t t = off[v][c]; off[v][c] = base; base = (uint16_t)(base + t); }
        csize[c] = base;
        exoff[c] = (base > CAP) ? (uint16_t)(base - CAP) : 0;
        ufoff[c] = (base < CAP) ? (uint16_t)(CAP - base) : 0;
    }
    __syncthreads();

    // Hillis-Steele inclusive scans over cells (all threads hit the syncs)
    for (int d = 1; d < CELLS; d <<= 1) {
        uint16_t ve = 0, vu = 0;
        if (tid < CELLS && tid >= d) { ve = exoff[tid - d]; vu = ufoff[tid - d]; }
        __syncthreads();
        if (tid < CELLS && tid >= d) { exoff[tid] = (uint16_t)(exoff[tid] + ve); ufoff[tid] = (uint16_t)(ufoff[tid] + vu); }
        __syncthreads();
    }

    // emit unfilled positions, grouped by cell (deterministic order)
    if (tid < CELLS) {
        int c = tid, t = c >> 4, s = c & 15;
        int sz  = csize[c];
        int ufc = (sz < CAP) ? CAP - sz : 0;
        int base = ufoff[c] - ufc;                     // exclusive offset
        for (int m = sz; m < CAP; m++) {
            int p = (((s - t) & 15) + 16 * m) * 16 + t;
            ufp[base + (m - sz)] = (uint16_t)p;
        }
    }
    __syncthreads();

    // assign positions
#pragma unroll
    for (int k = 0; k < ITEMS; k++) {
        int j = k * 1024 + tid;
        int cell = mycell[k];
        int grank = off[k * 32 + w][cell] + mylr[k];
        int t = cell >> 4, s = cell & 15;
        int p;
        if (grank < CAP) {
            p = (((s - t) & 15) + 16 * grank) * 16 + t;
        } else {
            int exc    = csize[cell] - CAP;            // > 0 here
            int exbase = exoff[cell] - exc;            // exclusive offset
            p = ufp[exbase + (grank - CAP)];
        }
        perm[blockIdx.x * D + p] = (uint16_t)j;
        if (inv) inv[blockIdx.x * D + j] = (uint16_t)p;
    }
}

// ---- merge: build permuted, index-remapped metadata ----------------------
__global__ void merge_meta_kernel()
{
    int j = blockIdx.x * blockDim.x + threadIdx.x;
    if (j >= NNEUR) return;
    if (j < D1) {
        int o = d_perm1[j];
        g_idx[j] = s_idx[o];                 // refs into xs: unpermuted
        g_c01[j] = s_c01[o];
        g_c23[j] = s_c23[o];
    } else if (j < D1 + D2) {
        int o = D1 + d_perm2[j - D1];
        uint32_t pk = s_idx[o];
        uint32_t a = d_inv1[pk & 0xffffu], b = d_inv1[pk >> 16];
        g_idx[j] = a | (b << 16);
        g_c01[j] = s_c01[o];
        g_c23[j] = s_c23[o];
    } else {
        int p = j - D1 - D2;
        int g = p >> 10;
        int o = D1 + D2 + (g << 10) + d_perm3[(g << 10) + (p & 1023)];
        uint32_t pk = s_idx[o];
        uint32_t a = d_inv2[pk & 0xffffu], b = d_inv2[pk >> 16];
        g_idx[j] = a | (b << 16);
        g_c01[j] = s_c01[o];
        g_c23[j] = s_c23[o];
    }
}

// -------- main kernel: whole network resident in shared memory (unchanged) --

struct NeuronIn {
    uint32_t pk, u01, u23;
    uint2 a, b;
};

__device__ __forceinline__ void fetch_neuron(const uint2* __restrict__ src,
                                             int mj, NeuronIn& n)
{
    n.pk  = __ldg(&g_idx[mj]);
    n.u01 = __ldg(&g_c01[mj]);
    n.u23 = __ldg(&g_c23[mj]);
    n.a = src[n.pk & 0xffffu];
    n.b = src[n.pk >> 16];
}

__device__ __forceinline__ uint2 neuron_math(const NeuronIn& n)
{
    float2 c01 = __half22float2(*reinterpret_cast<const __half2*>(&n.u01));
    float2 c23 = __half22float2(*reinterpret_cast<const __half2*>(&n.u23));
    uint2 o;
#pragma unroll
    for (int r = 0; r < R2; r++) {
        uint32_t ua = (r == 0) ? n.a.x : n.a.y;
        uint32_t ub = (r == 0) ? n.b.x : n.b.y;
        float2 a = __half22float2(*reinterpret_cast<const __half2*>(&ua));
        float2 b = __half22float2(*reinterpret_cast<const __half2*>(&ub));
        float o0 = fmaf(fmaf(c23.y, b.x, c01.y), a.x, fmaf(c23.x, b.x, c01.x));
        float o1 = fmaf(fmaf(c23.y, b.y, c01.y), a.y, fmaf(c23.x, b.y, c01.x));
        __half2 h = __floats2half2_rn(o0, o1);
        uint32_t uh = *reinterpret_cast<uint32_t*>(&h);
        if (r == 0) o.x = uh; else o.y = uh;
    }
    return o;
}

__device__ __forceinline__ void run_layer(const uint2* __restrict__ src,
                                          uint2* __restrict__ dst,
                                          int metaBase, int D, int tid)
{
    const int iters = D / NTHREADS;
    NeuronIn cur, nxt;
    int j = tid;
    fetch_neuron(src, metaBase + j, cur);
#pragma unroll 2
    for (int it = 0; it < iters - 1; it++) {
        fetch_neuron(src, metaBase + j + NTHREADS, nxt);
        dst[j] = neuron_math(cur);
        cur = nxt;
        j += NTHREADS;
    }
    dst[j] = neuron_math(cur);
}

__global__ void __launch_bounds__(NTHREADS, 1)
diff_logic_main(const float* __restrict__ x, float* __restrict__ out)
{
    extern __shared__ __align__(16) uint32_t smem_raw[];
    uint2* xs = reinterpret_cast<uint2*>(smem_raw);   // D0 slots
    uint2* h1 = xs + D0;                              // D1 slots
    uint2* h2 = h1 + D1;                              // D2 slots
    float* wacc = reinterpret_cast<float*>(h2 + D2);  // KCLS*NWARP*ROWS floats

    const int tid  = threadIdx.x;
    const int row0 = blockIdx.x * ROWS;

    {
        int col = tid;                                // D0 == NTHREADS == 1024
        float v0 = x[(size_t)(row0 + 0) * D0 + col];
        float v1 = x[(size_t)(row0 + 1) * D0 + col];
        float v2 = x[(size_t)(row0 + 2) * D0 + col];
        float v3 = x[(size_t)(row0 + 3) * D0 + col];
        __half2 p0 = __floats2half2_rn(v0, v1);
        __half2 p1 = __floats2half2_rn(v2, v3);
        uint2 slot;
        slot.x = *reinterpret_cast<uint32_t*>(&p0);
        slot.y = *reinterpret_cast<uint32_t*>(&p1);
        xs[col] = slot;
    }
    __syncthreads();

    run_layer(xs, h1, 0, D1, tid);
    __syncthreads();
    run_layer(h1, h2, D1, D2, tid);
    __syncthreads();

    const int lane = tid & 31;
    const int warp = tid >> 5;

    for (int g = 0; g < KCLS; g++) {
        float acc[ROWS];
#pragma unroll
        for (int r = 0; r < ROWS; r++) acc[r] = 0.f;
        {
            int mj = D1 + D2 + g * GRP + tid;
            NeuronIn n;
            fetch_neuron(h2, mj, n);
            float2 c01 = __half22float2(*reinterpret_cast<const __half2*>(&n.u01));
            float2 c23 = __half22float2(*reinterpret_cast<const __half2*>(&n.u23));
#pragma unroll
            for (int r = 0; r < R2; r++) {
                uint32_t ua = (r == 0) ? n.a.x : n.a.y;
                uint32_t ub = (r == 0) ? n.b.x : n.b.y;
                float2 a = __half22float2(*reinterpret_cast<const __half2*>(&ua));
                float2 b = __half22float2(*reinterpret_cast<const __half2*>(&ub));
                acc[2 * r + 0] += fmaf(fmaf(c23.y, b.x, c01.y), a.x, fmaf(c23.x, b.x, c01.x));
                acc[2 * r + 1] += fmaf(fmaf(c23.y, b.y, c01.y), a.y, fmaf(c23.x, b.y, c01.x));
            }
        }
#pragma unroll
        for (int r = 0; r < ROWS; r++) {
#pragma unroll
            for (int off = 16; off > 0; off >>= 1)
                acc[r] += __shfl_down_sync(0xffffffffu, acc[r], off);
        }
        if (lane == 0) {
#pragma unroll
            for (int r = 0; r < ROWS; r++)
                wacc[(g * NWARP + warp) * ROWS + r] = acc[r];
        }
    }
    __syncthreads();

    if (tid < KCLS * ROWS) {
        int g = tid / ROWS;
        int r = tid - g * ROWS;
        float s = 0.f;
#pragma unroll
        for (int w = 0; w < NWARP; w++)
            s += wacc[(g * NWARP + w) * ROWS + r];
        out[(size_t)(row0 + r) * KCLS + g] = s * (1.f / TAU);
    }
}

// -----------------------------------------------------------------------------

extern "C" void kernel_launch(void* const* d_in, const int* in_sizes, int n_in,
                              void* d_out, int out_size)
{
    (void)in_sizes; (void)n_in; (void)out_size;
    const float* x  = (const float*)d_in[0];
    const float* w1 = (const float*)d_in[1];
    const float* w2 = (const float*)d_in[2];
    const float* w3 = (const float*)d_in[3];
    const int* ia1 = (const int*)d_in[4];
    const int* ib1 = (const int*)d_in[5];
    const int* ia2 = (const int*)d_in[6];
    const int* ib2 = (const int*)d_in[7];
    const int* ia3 = (const int*)d_in[8];
    const int* ib3 = (const int*)d_in[9];
    float* out = (float*)d_out;

    precompute_kernel<<<(NNEUR + 255) / 256, 256>>>(w1, w2, w3, ia1, ib1, ia2, ib2, ia3, ib3);

    // permutation builders
    uint16_t *perm1, *inv1, *perm2, *inv2, *perm3;
    cudaGetSymbolAddress((void**)&perm1, d_perm1);
    cudaGetSymbolAddress((void**)&inv1,  d_inv1);
    cudaGetSymbolAddress((void**)&perm2, d_perm2);
    cudaGetSymbolAddress((void**)&inv2,  d_inv2);
    cudaGetSymbolAddress((void**)&perm3, d_perm3);

    size_t smP1 = ((size_t)(8192 / 32) * CELLS + 3 * CELLS + 8192) * sizeof(uint16_t); // ~149 KB
    size_t smP3 = ((size_t)(1024 / 32) * CELLS + 3 * CELLS + 1024) * sizeof(uint16_t); // ~20 KB
    cudaFuncSetAttribute(build_perm_kernel<8192>, cudaFuncAttributeMaxDynamicSharedMemorySize, (int)smP1);
    cudaFuncSetAttribute(build_perm_kernel<1024>, cudaFuncAttributeMaxDynamicSharedMemorySize, (int)smP3);

    build_perm_kernel<8192><<<1, 1024, smP1>>>(0,        nullptr, perm1, inv1);
    build_perm_kernel<8192><<<1, 1024, smP1>>>(D1,       inv1,    perm2, inv2);
    build_perm_kernel<1024><<<KCLS, 1024, smP3>>>(D1 + D2, inv2,   perm3, nullptr);
    merge_meta_kernel<<<(NNEUR + 255) / 256, 256>>>();

    size_t smem = (size_t)(D0 + D1 + D2) * sizeof(uint2)
                + (size_t)(KCLS * NWARP * ROWS) * sizeof(float);   // 144,384 B
    cudaFuncSetAttribute(diff_logic_main, cudaFuncAttributeMaxDynamicSharedMemorySize, (int)smem);

    diff_logic_main<<<B_SZ / ROWS, NTHREADS, smem>>>(x, out);
}